// round 14
// baseline (speedup 1.0000x reference)
#include <cuda_runtime.h>
#include <cstdint>

#define NODES 20000
#define BATCH 32
#define FEAT  64
#define EIG   16
#define NOUT  64

// k1: 50 chunks x 400 nodes x 16 batch-pairs = 800 blocks (R12 passing code,
// constants halved: more blocks, fewer barriers per block -> k3-like regime)
#define NCHUNK 50
#define CH1    400
#define PN     40
#define NPAN   10
#define PFL    5760          // floats per panel buffer: xA 2560 | xB 2560 | V 640
#define XB_OFF 2560
#define V_OFF  5120

// k3: 157 tiles x 128 nodes (last tile 32), 16 batch-pairs
#define TN3    128
#define NBLK3  157

typedef unsigned long long ull;

// Scratch (static device globals: allocation-free per harness rules)
// g_zpart[c][bp][r][bb][i][f]: 50*16*4*2048 floats = 26.2 MB
__device__ float g_zpart[(size_t)NCHUNK * 16 * 4 * 2048];
__device__ float g_z[BATCH * FEAT * EIG];                      // 128 KB
__device__ float g_w[BATCH * NOUT * EIG];                      // 128 KB

// ---- packed fp32x2 helpers ----
__device__ __forceinline__ ull pack2(float lo, float hi) {
    ull r; asm("mov.b64 %0, {%1, %2};" : "=l"(r) : "f"(lo), "f"(hi)); return r;
}
__device__ __forceinline__ float2 unpack2(ull v) {
    float2 r; asm("mov.b64 {%0, %1}, %2;" : "=f"(r.x), "=f"(r.y) : "l"(v)); return r;
}
__device__ __forceinline__ ull ffma2(ull a, ull b, ull c) {
    ull d; asm("fma.rn.f32x2 %0, %1, %2, %3;" : "=l"(d) : "l"(a), "l"(b), "l"(c)); return d;
}
__device__ __forceinline__ ull fadd2(ull a, ull b) {
    ull d; asm("add.rn.f32x2 %0, %1, %2;" : "=l"(d) : "l"(a), "l"(b)); return d;
}

// ---- cp.async helpers ----
__device__ __forceinline__ void cpa16(uint32_t dst, const void* src) {
    asm volatile("cp.async.cg.shared.global [%0], [%1], 16;" :: "r"(dst), "l"(src));
}
__device__ __forceinline__ void cpa_commit() {
    asm volatile("cp.async.commit_group;");
}
__device__ __forceinline__ void cpa_wait0() {
    asm volatile("cp.async.wait_group 0;");
}

// ============================================================================
// Stage 1: z[b,i,f] = sum_m V[m,f] * x[b,m,i]  -- R12's PASSING kernel with
// halved chunks: block = (400-node chunk, batch-pair), 800 blocks total.
// Thread owns 2i x 2b x 16f (32 ull accum). Per node: V via 4 uniform
// LDS.128 (amortized over 2 batches) + x via 2 lane-distinct LDS.64 + 32
// FFMA2. x/V staged via cp.async double-buffered 40-node panels.
// Epilogue: one pairwise warp-reduce (8->4, proven in R12); 4 partials/block.
// ============================================================================
__global__ __launch_bounds__(256)
void k1_project(const float* __restrict__ x, const float* __restrict__ V) {
    __shared__ __align__(16) float sm[2 * PFL];   // 46.08 KB
    const int c  = blockIdx.x;          // chunk 0..NCHUNK-1
    const int bp = blockIdx.y;          // batch pair 0..15
    const int b0 = bp * 2;
    const int m0 = c * CH1;
    const int tid = threadIdx.x;
    const int w = tid >> 5, lane = tid & 31;
    const uint32_t smb = (uint32_t)__cvta_generic_to_shared(sm);

    const float* xA0 = x + ((size_t)b0 * NODES) * FEAT;
    const float* xB0 = xA0 + (size_t)NODES * FEAT;

    // ---- stage panel p into buffer (p&1) ----
    auto stage = [&](int p) {
        const int mp = m0 + p * PN;
        const uint32_t bufb = smb + (uint32_t)((p & 1) * PFL * 4);
        const float* sA = xA0 + (size_t)mp * FEAT;
        const float* sB = xB0 + (size_t)mp * FEAT;
        #pragma unroll
        for (int r = 0; r < 3; r++) {
            int i = tid + r * 256;
            if (i < 640) cpa16(bufb + i * 16, sA + i * 4);
        }
        #pragma unroll
        for (int r = 0; r < 3; r++) {
            int i = tid + r * 256;
            if (i < 640) cpa16(bufb + XB_OFF * 4 + i * 16, sB + i * 4);
        }
        if (tid < 160) cpa16(bufb + V_OFF * 4 + tid * 16, V + (size_t)mp * EIG + tid * 4);
        cpa_commit();
    };

    ull zA0[8], zA1[8], zB0[8], zB1[8];
    #pragma unroll
    for (int k = 0; k < 8; k++) { zA0[k]=0; zA1[k]=0; zB0[k]=0; zB1[k]=0; }

    stage(0);
    for (int p = 0; p < NPAN; p++) {
        cpa_wait0();
        __syncthreads();                 // panel p visible; buf (p+1)&1 free
        if (p + 1 < NPAN) stage(p + 1);  // overlaps with compute(p)
        const float* buf = sm + (p & 1) * PFL;
        #pragma unroll
        for (int t = 0; t < 5; t++) {
            const int n = t * 8 + w;     // this warp's node within the panel
            float2 xa = *(const float2*)(buf + n * FEAT + 2 * lane);
            float2 xb = *(const float2*)(buf + XB_OFF + n * FEAT + 2 * lane);
            const ulonglong2* vp = (const ulonglong2*)(buf + V_OFF + n * EIG);
            ulonglong2 v01 = vp[0], v23 = vp[1], v45 = vp[2], v67 = vp[3];
            ull q[8] = {v01.x, v01.y, v23.x, v23.y, v45.x, v45.y, v67.x, v67.y};
            ull xa0 = pack2(xa.x, xa.x), xa1 = pack2(xa.y, xa.y);
            ull xb0 = pack2(xb.x, xb.x), xb1 = pack2(xb.y, xb.y);
            #pragma unroll
            for (int k = 0; k < 8; k++) {
                zA0[k] = ffma2(xa0, q[k], zA0[k]);
                zA1[k] = ffma2(xa1, q[k], zA1[k]);
                zB0[k] = ffma2(xb0, q[k], zB0[k]);
                zB1[k] = ffma2(xb1, q[k], zB1[k]);
            }
        }
    }
    __syncthreads();   // done with panel buffers; reuse sm for reduction

    // ---- pairwise warp reduce: warps 4-7 stash, warps 0-3 add partner ----
    // lane row stride 66 floats (264B: 8B-aligned, 2-way bank spread)
    if (w >= 4) {
        float* pb = sm + (w - 4) * 2112 + lane * 66;
        #pragma unroll
        for (int k = 0; k < 8; k++) {
            *(ull*)(pb + 2 * k)      = zA0[k];
            *(ull*)(pb + 16 + 2 * k) = zA1[k];
            *(ull*)(pb + 32 + 2 * k) = zB0[k];
            *(ull*)(pb + 48 + 2 * k) = zB1[k];
        }
    }
    __syncthreads();
    if (w < 4) {
        const float* pb = sm + w * 2112 + lane * 66;
        #pragma unroll
        for (int k = 0; k < 8; k++) {
            zA0[k] = fadd2(zA0[k], *(const ull*)(pb + 2 * k));
            zA1[k] = fadd2(zA1[k], *(const ull*)(pb + 16 + 2 * k));
            zB0[k] = fadd2(zB0[k], *(const ull*)(pb + 32 + 2 * k));
            zB1[k] = fadd2(zB1[k], *(const ull*)(pb + 48 + 2 * k));
        }
        // write partial z: g_zpart[((c*16+bp)*4 + w)*2048 + bb*1024 + i*16 + f]
        float* gz = g_zpart + (((size_t)c * 16 + bp) * 4 + w) * 2048;
        #pragma unroll
        for (int bb = 0; bb < 2; bb++) {
            ull* zi0 = bb ? zB0 : zA0;
            ull* zi1 = bb ? zB1 : zA1;
            #pragma unroll
            for (int ii = 0; ii < 2; ii++) {
                ull* z = ii ? zi1 : zi0;
                float* row = gz + bb * 1024 + (2 * lane + ii) * EIG;
                #pragma unroll
                for (int q4 = 0; q4 < 4; q4++) {
                    float2 u0 = unpack2(z[2 * q4]);
                    float2 u1 = unpack2(z[2 * q4 + 1]);
                    *(float4*)(row + q4 * 4) = make_float4(u0.x, u0.y, u1.x, u1.y);
                }
            }
        }
    }
}

// ============================================================================
// Stage 1b: reduce partial z over 50 chunks x 4 warp-groups (fixed order)
// ============================================================================
__global__ __launch_bounds__(256)
void k1_reduce() {
    const int q = blockIdx.x * 256 + threadIdx.x;   // over 8192 float4
    const int b = q >> 8, rem = q & 255;
    const int bp = b >> 1, bb = b & 1;
    const float4* zp = (const float4*)g_zpart;
    float4 s = make_float4(0.f, 0.f, 0.f, 0.f);
    for (int c = 0; c < NCHUNK; c++) {
        #pragma unroll
        for (int r = 0; r < 4; r++) {
            float4 v = zp[(((size_t)c * 16 + bp) * 4 + r) * 512 + bb * 256 + rem];
            s.x += v.x; s.y += v.y; s.z += v.z; s.w += v.w;
        }
    }
    ((float4*)g_z)[q] = s;
}

// ============================================================================
// Stage 2: w[b,j,e] = sum_{i,f} G[j,i,e,f] * z[b,i,f]
// ============================================================================
__global__ __launch_bounds__(128)
void k2_mix(const float* __restrict__ G) {
    const int bg = blockIdx.x;     // 0..3
    const int j  = blockIdx.y;     // 0..63
    const int tid = threadIdx.x;   // 128
    const int bl = tid >> 4;       // 0..7
    const int e  = tid & 15;
    const float* Gje  = G + (size_t)j * (FEAT * EIG * EIG) + e * EIG;
    const float* zrow = g_z + ((size_t)bg * 8 + bl) * (FEAT * EIG);
    ull acc0 = 0ULL, acc1 = 0ULL, acc2 = 0ULL, acc3 = 0ULL;
    #pragma unroll 8
    for (int i = 0; i < FEAT; i++) {
        const ulonglong2* gp = (const ulonglong2*)(Gje + (size_t)i * (EIG * EIG));
        const ulonglong2* zq = (const ulonglong2*)(zrow + i * EIG);
        ulonglong2 g0 = gp[0], g1 = gp[1], g2 = gp[2], g3 = gp[3];
        ulonglong2 z0 = zq[0], z1 = zq[1], z2 = zq[2], z3 = zq[3];
        acc0 = ffma2(g0.x, z0.x, acc0);
        acc1 = ffma2(g0.y, z0.y, acc1);
        acc2 = ffma2(g1.x, z1.x, acc2);
        acc3 = ffma2(g1.y, z1.y, acc3);
        acc0 = ffma2(g2.x, z2.x, acc0);
        acc1 = ffma2(g2.y, z2.y, acc1);
        acc2 = ffma2(g3.x, z3.x, acc2);
        acc3 = ffma2(g3.y, z3.y, acc3);
    }
    float2 f0 = unpack2(acc0), f1 = unpack2(acc1);
    float2 f2 = unpack2(acc2), f3 = unpack2(acc3);
    g_w[((size_t)bg * 8 + bl) * (NOUT * EIG) + j * EIG + e] =
        ((f0.x + f0.y) + (f1.x + f1.y)) + ((f2.x + f2.y) + (f3.x + f3.y));
}

// ============================================================================
// Stage 3: out[b,n,j] = sum_e V[n,e] * w[b,j,e]   (R11/R12 verbatim: 40.6us)
// ============================================================================
__global__ __launch_bounds__(256)
void k3_expand(const float* __restrict__ V, float* __restrict__ out) {
    __shared__ __align__(16) float vs[TN3 * EIG];        // 8 KB
    __shared__ __align__(16) float wsT[2][EIG * 65];     // 8.3 KB padded transpose
    const int b0 = blockIdx.y * 2;
    const int n0 = blockIdx.x * TN3;
    const int Nloc = (NODES - n0 < TN3) ? (NODES - n0) : TN3;   // 128 or 32
    const int tid = threadIdx.x;
    const int jp = tid & 31, nb = tid >> 5;

    #pragma unroll
    for (int bb = 0; bb < 2; bb++) {
        float4 fw = ((const float4*)(g_w + (size_t)(b0 + bb) * NOUT * EIG))[tid];
        int j = tid >> 2, e0 = (tid & 3) * 4;
        wsT[bb][(e0 + 0) * 65 + j] = fw.x;
        wsT[bb][(e0 + 1) * 65 + j] = fw.y;
        wsT[bb][(e0 + 2) * 65 + j] = fw.z;
        wsT[bb][(e0 + 3) * 65 + j] = fw.w;
    }
    {
        const float4* src = (const float4*)(V + (size_t)n0 * EIG);
        for (int idx = tid; idx < Nloc * 4; idx += 256) ((float4*)vs)[idx] = src[idx];
    }
    __syncthreads();

    ull wA0[8], wA1[8], wB0[8], wB1[8];
    #pragma unroll
    for (int k = 0; k < 8; k++) {
        wA0[k] = pack2(wsT[0][(2*k)*65 + 2*jp],     wsT[0][(2*k+1)*65 + 2*jp]);
        wA1[k] = pack2(wsT[0][(2*k)*65 + 2*jp + 1], wsT[0][(2*k+1)*65 + 2*jp + 1]);
        wB0[k] = pack2(wsT[1][(2*k)*65 + 2*jp],     wsT[1][(2*k+1)*65 + 2*jp]);
        wB1[k] = pack2(wsT[1][(2*k)*65 + 2*jp + 1], wsT[1][(2*k+1)*65 + 2*jp + 1]);
    }

    float* obA = out + (size_t)(b0)     * NODES * NOUT + (size_t)n0 * NOUT + 2 * jp;
    float* obB = out + (size_t)(b0 + 1) * NODES * NOUT + (size_t)n0 * NOUT + 2 * jp;

    #pragma unroll 4
    for (int t = 0; t < 16; t++) {
        const int n = nb * 16 + t;               // warp-uniform
        if (n >= Nloc) break;
        const ulonglong2* vp = (const ulonglong2*)(vs + n * EIG);
        ulonglong2 va = vp[0], vb = vp[1];
        ull aA0 = 0, aA1 = 0, aB0 = 0, aB1 = 0;
        aA0 = ffma2(va.x, wA0[0], aA0);  aA1 = ffma2(va.x, wA1[0], aA1);
        aB0 = ffma2(va.x, wB0[0], aB0);  aB1 = ffma2(va.x, wB1[0], aB1);
        aA0 = ffma2(va.y, wA0[1], aA0);  aA1 = ffma2(va.y, wA1[1], aA1);
        aB0 = ffma2(va.y, wB0[1], aB0);  aB1 = ffma2(va.y, wB1[1], aB1);
        aA0 = ffma2(vb.x, wA0[2], aA0);  aA1 = ffma2(vb.x, wA1[2], aA1);
        aB0 = ffma2(vb.x, wB0[2], aB0);  aB1 = ffma2(vb.x, wB1[2], aB1);
        aA0 = ffma2(vb.y, wA0[3], aA0);  aA1 = ffma2(vb.y, wA1[3], aA1);
        aB0 = ffma2(vb.y, wB0[3], aB0);  aB1 = ffma2(vb.y, wB1[3], aB1);
        ulonglong2 vc = vp[2], vd = vp[3];
        aA0 = ffma2(vc.x, wA0[4], aA0);  aA1 = ffma2(vc.x, wA1[4], aA1);
        aB0 = ffma2(vc.x, wB0[4], aB0);  aB1 = ffma2(vc.x, wB1[4], aB1);
        aA0 = ffma2(vc.y, wA0[5], aA0);  aA1 = ffma2(vc.y, wA1[5], aA1);
        aB0 = ffma2(vc.y, wB0[5], aB0);  aB1 = ffma2(vc.y, wB1[5], aB1);
        aA0 = ffma2(vd.x, wA0[6], aA0);  aA1 = ffma2(vd.x, wA1[6], aA1);
        aB0 = ffma2(vd.x, wB0[6], aB0);  aB1 = ffma2(vd.x, wB1[6], aB1);
        aA0 = ffma2(vd.y, wA0[7], aA0);  aA1 = ffma2(vd.y, wA1[7], aA1);
        aB0 = ffma2(vd.y, wB0[7], aB0);  aB1 = ffma2(vd.y, wB1[7], aB1);
        float2 rA0 = unpack2(aA0), rA1 = unpack2(aA1);
        float2 rB0 = unpack2(aB0), rB1 = unpack2(aB1);
        *(float2*)(obA + (size_t)n * NOUT) = make_float2(rA0.x + rA0.y, rA1.x + rA1.y);
        *(float2*)(obB + (size_t)n * NOUT) = make_float2(rB0.x + rB0.y, rB1.x + rB1.y);
    }
}

extern "C" void kernel_launch(void* const* d_in, const int* in_sizes, int n_in,
                              void* d_out, int out_size) {
    const float* x = (const float*)d_in[0];   // (32, 20000, 64) fp32
    const float* V = (const float*)d_in[1];   // (20000, 16)     fp32
    const float* G = (const float*)d_in[2];   // (64, 64, 16, 16) fp32
    float* out = (float*)d_out;               // (32, 20000, 64) fp32

    k1_project<<<dim3(NCHUNK, 16), 256>>>(x, V);
    k1_reduce<<<32, 256>>>();
    k2_mix<<<dim3(4, NOUT), 128>>>(G);
    k3_expand<<<dim3(NBLK3, BATCH / 2), 256>>>(V, out);
}

// round 15
// speedup vs baseline: 1.0554x; 1.0554x over previous
#include <cuda_runtime.h>
#include <cstdint>

#define NODES 20000
#define BATCH 32
#define FEAT  64
#define EIG   16
#define NOUT  64

// k1: 25 chunks x 800 nodes x 16 batch-pairs = 400 blocks (R12's winning grid)
// Panels of 16 nodes, TRIPLE-buffered cp.async, wait_group 1 (2 in flight).
#define NCHUNK 25
#define CH1    800
#define PN     16
#define NPAN   50
#define PFL    2304          // floats per panel buffer: xA 1024 | xB 1024 | V 256
#define XB_OFF 1024
#define V_OFF  2048
#define SM1    8448          // smem floats: >= 3*PFL (6912) and epilogue 4*2112 (8448)

// k3: 157 tiles x 128 nodes (last tile 32), 16 batch-pairs
#define TN3    128
#define NBLK3  157

typedef unsigned long long ull;

// Scratch (static device globals: allocation-free per harness rules)
// g_zpart[c][bp][r][bb][i][f]: 25*16*4*2048 floats = 13.1 MB
__device__ float g_zpart[(size_t)NCHUNK * 16 * 4 * 2048];
__device__ float g_z[BATCH * FEAT * EIG];                      // 128 KB
__device__ float g_w[BATCH * NOUT * EIG];                      // 128 KB

// ---- packed fp32x2 helpers ----
__device__ __forceinline__ ull pack2(float lo, float hi) {
    ull r; asm("mov.b64 %0, {%1, %2};" : "=l"(r) : "f"(lo), "f"(hi)); return r;
}
__device__ __forceinline__ float2 unpack2(ull v) {
    float2 r; asm("mov.b64 {%0, %1}, %2;" : "=f"(r.x), "=f"(r.y) : "l"(v)); return r;
}
__device__ __forceinline__ ull ffma2(ull a, ull b, ull c) {
    ull d; asm("fma.rn.f32x2 %0, %1, %2, %3;" : "=l"(d) : "l"(a), "l"(b), "l"(c)); return d;
}
__device__ __forceinline__ ull fadd2(ull a, ull b) {
    ull d; asm("add.rn.f32x2 %0, %1, %2;" : "=l"(d) : "l"(a), "l"(b)); return d;
}

// ---- cp.async helpers ----
__device__ __forceinline__ void cpa16(uint32_t dst, const void* src) {
    asm volatile("cp.async.cg.shared.global [%0], [%1], 16;" :: "r"(dst), "l"(src));
}
__device__ __forceinline__ void cpa_commit() {
    asm volatile("cp.async.commit_group;");
}
__device__ __forceinline__ void cpa_wait0() {
    asm volatile("cp.async.wait_group 0;");
}
__device__ __forceinline__ void cpa_wait1() {
    asm volatile("cp.async.wait_group 1;");
}

// ============================================================================
// Stage 1: z[b,i,f] = sum_m V[m,f] * x[b,m,i]  -- R12 passing base with a
// DEEPER cp.async pipeline: 3 buffers x 16-node panels, wait_group 1 keeps
// TWO fetches in flight while computing a third (R12's 2-deep/wait0 pipeline
// exposed ~1-2K cyc of DRAM latency EVERY panel -- the measured k1 gap; R14
// showed barriers/blocks were not the cause). Inner loop / accumulators /
// epilogue / partial layout byte-identical to R12.
// ============================================================================
__global__ __launch_bounds__(256)
void k1_project(const float* __restrict__ x, const float* __restrict__ V) {
    __shared__ __align__(16) float sm[SM1];   // 33.8 KB
    const int c  = blockIdx.x;          // chunk 0..24
    const int bp = blockIdx.y;          // batch pair 0..15
    const int b0 = bp * 2;
    const int m0 = c * CH1;
    const int tid = threadIdx.x;
    const int w = tid >> 5, lane = tid & 31;
    const uint32_t smb = (uint32_t)__cvta_generic_to_shared(sm);

    const float* xA0 = x + ((size_t)b0 * NODES) * FEAT;
    const float* xB0 = xA0 + (size_t)NODES * FEAT;

    // ---- stage panel p into buffer (p % 3): one cp.async per thread per tile
    auto stage = [&](int p) {
        const int mp = m0 + p * PN;
        const uint32_t bufb = smb + (uint32_t)((p % 3) * PFL * 4);
        cpa16(bufb + tid * 16, xA0 + (size_t)mp * FEAT + tid * 4);           // 256 f4
        cpa16(bufb + XB_OFF * 4 + tid * 16, xB0 + (size_t)mp * FEAT + tid * 4);
        if (tid < 64)
            cpa16(bufb + V_OFF * 4 + tid * 16, V + (size_t)mp * EIG + tid * 4);
        cpa_commit();
    };

    ull zA0[8], zA1[8], zB0[8], zB1[8];
    #pragma unroll
    for (int k = 0; k < 8; k++) { zA0[k]=0; zA1[k]=0; zB0[k]=0; zB1[k]=0; }

    stage(0);
    stage(1);
    for (int p = 0; p < NPAN; p++) {
        if (p + 2 < NPAN) cpa_wait1();   // panel p done; p+1 still in flight
        else              cpa_wait0();   // tail: drain everything
        __syncthreads();                 // all warps past compute(p-1)
        if (p + 2 < NPAN) stage(p + 2);  // writes buf (p+2)%3 = (p-1)%3, now free
        const float* buf = sm + (p % 3) * PFL;
        #pragma unroll
        for (int t = 0; t < 2; t++) {
            const int n = t * 8 + w;     // this warp's node within the panel
            float2 xa = *(const float2*)(buf + n * FEAT + 2 * lane);
            float2 xb = *(const float2*)(buf + XB_OFF + n * FEAT + 2 * lane);
            const ulonglong2* vp = (const ulonglong2*)(buf + V_OFF + n * EIG);
            ulonglong2 v01 = vp[0], v23 = vp[1], v45 = vp[2], v67 = vp[3];
            ull q[8] = {v01.x, v01.y, v23.x, v23.y, v45.x, v45.y, v67.x, v67.y};
            ull xa0 = pack2(xa.x, xa.x), xa1 = pack2(xa.y, xa.y);
            ull xb0 = pack2(xb.x, xb.x), xb1 = pack2(xb.y, xb.y);
            #pragma unroll
            for (int k = 0; k < 8; k++) {
                zA0[k] = ffma2(xa0, q[k], zA0[k]);
                zA1[k] = ffma2(xa1, q[k], zA1[k]);
                zB0[k] = ffma2(xb0, q[k], zB0[k]);
                zB1[k] = ffma2(xb1, q[k], zB1[k]);
            }
        }
    }
    __syncthreads();   // done with panel buffers; reuse sm for reduction

    // ---- pairwise warp reduce: warps 4-7 stash, warps 0-3 add partner ----
    // (R12 verbatim) lane row stride 66 floats
    if (w >= 4) {
        float* pb = sm + (w - 4) * 2112 + lane * 66;
        #pragma unroll
        for (int k = 0; k < 8; k++) {
            *(ull*)(pb + 2 * k)      = zA0[k];
            *(ull*)(pb + 16 + 2 * k) = zA1[k];
            *(ull*)(pb + 32 + 2 * k) = zB0[k];
            *(ull*)(pb + 48 + 2 * k) = zB1[k];
        }
    }
    __syncthreads();
    if (w < 4) {
        const float* pb = sm + w * 2112 + lane * 66;
        #pragma unroll
        for (int k = 0; k < 8; k++) {
            zA0[k] = fadd2(zA0[k], *(const ull*)(pb + 2 * k));
            zA1[k] = fadd2(zA1[k], *(const ull*)(pb + 16 + 2 * k));
            zB0[k] = fadd2(zB0[k], *(const ull*)(pb + 32 + 2 * k));
            zB1[k] = fadd2(zB1[k], *(const ull*)(pb + 48 + 2 * k));
        }
        // write partial z: g_zpart[((c*16+bp)*4 + w)*2048 + bb*1024 + i*16 + f]
        float* gz = g_zpart + (((size_t)c * 16 + bp) * 4 + w) * 2048;
        #pragma unroll
        for (int bb = 0; bb < 2; bb++) {
            ull* zi0 = bb ? zB0 : zA0;
            ull* zi1 = bb ? zB1 : zA1;
            #pragma unroll
            for (int ii = 0; ii < 2; ii++) {
                ull* z = ii ? zi1 : zi0;
                float* row = gz + bb * 1024 + (2 * lane + ii) * EIG;
                #pragma unroll
                for (int q4 = 0; q4 < 4; q4++) {
                    float2 u0 = unpack2(z[2 * q4]);
                    float2 u1 = unpack2(z[2 * q4 + 1]);
                    *(float4*)(row + q4 * 4) = make_float4(u0.x, u0.y, u1.x, u1.y);
                }
            }
        }
    }
}

// ============================================================================
// Stage 1b: reduce partial z over 25 chunks x 4 warp-groups (R12 verbatim)
// ============================================================================
__global__ __launch_bounds__(256)
void k1_reduce() {
    const int q = blockIdx.x * 256 + threadIdx.x;   // over 8192 float4
    const int b = q >> 8, rem = q & 255;
    const int bp = b >> 1, bb = b & 1;
    const float4* zp = (const float4*)g_zpart;
    float4 s = make_float4(0.f, 0.f, 0.f, 0.f);
    for (int c = 0; c < NCHUNK; c++) {
        #pragma unroll
        for (int r = 0; r < 4; r++) {
            float4 v = zp[(((size_t)c * 16 + bp) * 4 + r) * 512 + bb * 256 + rem];
            s.x += v.x; s.y += v.y; s.z += v.z; s.w += v.w;
        }
    }
    ((float4*)g_z)[q] = s;
}

// ============================================================================
// Stage 2: w[b,j,e] = sum_{i,f} G[j,i,e,f] * z[b,i,f]  (verbatim)
// ============================================================================
__global__ __launch_bounds__(128)
void k2_mix(const float* __restrict__ G) {
    const int bg = blockIdx.x;     // 0..3
    const int j  = blockIdx.y;     // 0..63
    const int tid = threadIdx.x;   // 128
    const int bl = tid >> 4;       // 0..7
    const int e  = tid & 15;
    const float* Gje  = G + (size_t)j * (FEAT * EIG * EIG) + e * EIG;
    const float* zrow = g_z + ((size_t)bg * 8 + bl) * (FEAT * EIG);
    ull acc0 = 0ULL, acc1 = 0ULL, acc2 = 0ULL, acc3 = 0ULL;
    #pragma unroll 8
    for (int i = 0; i < FEAT; i++) {
        const ulonglong2* gp = (const ulonglong2*)(Gje + (size_t)i * (EIG * EIG));
        const ulonglong2* zq = (const ulonglong2*)(zrow + i * EIG);
        ulonglong2 g0 = gp[0], g1 = gp[1], g2 = gp[2], g3 = gp[3];
        ulonglong2 z0 = zq[0], z1 = zq[1], z2 = zq[2], z3 = zq[3];
        acc0 = ffma2(g0.x, z0.x, acc0);
        acc1 = ffma2(g0.y, z0.y, acc1);
        acc2 = ffma2(g1.x, z1.x, acc2);
        acc3 = ffma2(g1.y, z1.y, acc3);
        acc0 = ffma2(g2.x, z2.x, acc0);
        acc1 = ffma2(g2.y, z2.y, acc1);
        acc2 = ffma2(g3.x, z3.x, acc2);
        acc3 = ffma2(g3.y, z3.y, acc3);
    }
    float2 f0 = unpack2(acc0), f1 = unpack2(acc1);
    float2 f2 = unpack2(acc2), f3 = unpack2(acc3);
    g_w[((size_t)bg * 8 + bl) * (NOUT * EIG) + j * EIG + e] =
        ((f0.x + f0.y) + (f1.x + f1.y)) + ((f2.x + f2.y) + (f3.x + f3.y));
}

// ============================================================================
// Stage 3: out[b,n,j] = sum_e V[n,e] * w[b,j,e]   (R11/R12 verbatim: ~41us)
// ============================================================================
__global__ __launch_bounds__(256)
void k3_expand(const float* __restrict__ V, float* __restrict__ out) {
    __shared__ __align__(16) float vs[TN3 * EIG];        // 8 KB
    __shared__ __align__(16) float wsT[2][EIG * 65];     // 8.3 KB padded transpose
    const int b0 = blockIdx.y * 2;
    const int n0 = blockIdx.x * TN3;
    const int Nloc = (NODES - n0 < TN3) ? (NODES - n0) : TN3;   // 128 or 32
    const int tid = threadIdx.x;
    const int jp = tid & 31, nb = tid >> 5;

    #pragma unroll
    for (int bb = 0; bb < 2; bb++) {
        float4 fw = ((const float4*)(g_w + (size_t)(b0 + bb) * NOUT * EIG))[tid];
        int j = tid >> 2, e0 = (tid & 3) * 4;
        wsT[bb][(e0 + 0) * 65 + j] = fw.x;
        wsT[bb][(e0 + 1) * 65 + j] = fw.y;
        wsT[bb][(e0 + 2) * 65 + j] = fw.z;
        wsT[bb][(e0 + 3) * 65 + j] = fw.w;
    }
    {
        const float4* src = (const float4*)(V + (size_t)n0 * EIG);
        for (int idx = tid; idx < Nloc * 4; idx += 256) ((float4*)vs)[idx] = src[idx];
    }
    __syncthreads();

    ull wA0[8], wA1[8], wB0[8], wB1[8];
    #pragma unroll
    for (int k = 0; k < 8; k++) {
        wA0[k] = pack2(wsT[0][(2*k)*65 + 2*jp],     wsT[0][(2*k+1)*65 + 2*jp]);
        wA1[k] = pack2(wsT[0][(2*k)*65 + 2*jp + 1], wsT[0][(2*k+1)*65 + 2*jp + 1]);
        wB0[k] = pack2(wsT[1][(2*k)*65 + 2*jp],     wsT[1][(2*k+1)*65 + 2*jp]);
        wB1[k] = pack2(wsT[1][(2*k)*65 + 2*jp + 1], wsT[1][(2*k+1)*65 + 2*jp + 1]);
    }

    float* obA = out + (size_t)(b0)     * NODES * NOUT + (size_t)n0 * NOUT + 2 * jp;
    float* obB = out + (size_t)(b0 + 1) * NODES * NOUT + (size_t)n0 * NOUT + 2 * jp;

    #pragma unroll 4
    for (int t = 0; t < 16; t++) {
        const int n = nb * 16 + t;               // warp-uniform
        if (n >= Nloc) break;
        const ulonglong2* vp = (const ulonglong2*)(vs + n * EIG);
        ulonglong2 va = vp[0], vb = vp[1];
        ull aA0 = 0, aA1 = 0, aB0 = 0, aB1 = 0;
        aA0 = ffma2(va.x, wA0[0], aA0);  aA1 = ffma2(va.x, wA1[0], aA1);
        aB0 = ffma2(va.x, wB0[0], aB0);  aB1 = ffma2(va.x, wB1[0], aB1);
        aA0 = ffma2(va.y, wA0[1], aA0);  aA1 = ffma2(va.y, wA1[1], aA1);
        aB0 = ffma2(va.y, wB0[1], aB0);  aB1 = ffma2(va.y, wB1[1], aB1);
        aA0 = ffma2(vb.x, wA0[2], aA0);  aA1 = ffma2(vb.x, wA1[2], aA1);
        aB0 = ffma2(vb.x, wB0[2], aB0);  aB1 = ffma2(vb.x, wB1[2], aB1);
        aA0 = ffma2(vb.y, wA0[3], aA0);  aA1 = ffma2(vb.y, wA1[3], aA1);
        aB0 = ffma2(vb.y, wB0[3], aB0);  aB1 = ffma2(vb.y, wB1[3], aB1);
        ulonglong2 vc = vp[2], vd = vp[3];
        aA0 = ffma2(vc.x, wA0[4], aA0);  aA1 = ffma2(vc.x, wA1[4], aA1);
        aB0 = ffma2(vc.x, wB0[4], aB0);  aB1 = ffma2(vc.x, wB1[4], aB1);
        aA0 = ffma2(vc.y, wA0[5], aA0);  aA1 = ffma2(vc.y, wA1[5], aA1);
        aB0 = ffma2(vc.y, wB0[5], aB0);  aB1 = ffma2(vc.y, wB1[5], aB1);
        aA0 = ffma2(vd.x, wA0[6], aA0);  aA1 = ffma2(vd.x, wA1[6], aA1);
        aB0 = ffma2(vd.x, wB0[6], aB0);  aB1 = ffma2(vd.x, wB1[6], aB1);
        aA0 = ffma2(vd.y, wA0[7], aA0);  aA1 = ffma2(vd.y, wA1[7], aA1);
        aB0 = ffma2(vd.y, wB0[7], aB0);  aB1 = ffma2(vd.y, wB1[7], aB1);
        float2 rA0 = unpack2(aA0), rA1 = unpack2(aA1);
        float2 rB0 = unpack2(aB0), rB1 = unpack2(aB1);
        *(float2*)(obA + (size_t)n * NOUT) = make_float2(rA0.x + rA0.y, rA1.x + rA1.y);
        *(float2*)(obB + (size_t)n * NOUT) = make_float2(rB0.x + rB0.y, rB1.x + rB1.y);
    }
}

extern "C" void kernel_launch(void* const* d_in, const int* in_sizes, int n_in,
                              void* d_out, int out_size) {
    const float* x = (const float*)d_in[0];   // (32, 20000, 64) fp32
    const float* V = (const float*)d_in[1];   // (20000, 16)     fp32
    const float* G = (const float*)d_in[2];   // (64, 64, 16, 16) fp32
    float* out = (float*)d_out;               // (32, 20000, 64) fp32

    k1_project<<<dim3(NCHUNK, 16), 256>>>(x, V);
    k1_reduce<<<32, 256>>>();
    k2_mix<<<dim3(4, NOUT), 128>>>(G);
    k3_expand<<<dim3(NBLK3, BATCH / 2), 256>>>(V, out);
}